// round 6
// baseline (speedup 1.0000x reference)
#include <cuda_runtime.h>
#include <cuda_bf16.h>

#define HIDDEN 512
#define MAX_LEN 4096
#define BATCH 32

#define V_BLOCKS 128     // blocks 0..127 compute v; rest compute energies
#define E_WARPS  16      // 512 threads -> 16 rows per energy block

// Scratch: v[b][h] = sum_o hidden[b][o] * W[o][h]   (Wᵀ·hidden per batch)
__device__ float4 g_v4[BATCH * (HIDDEN / 4)];  // 64 KB
__device__ int    g_vdone;                     // zero-init; reset by softmax

// ---------------------------------------------------------------------------
// Fused kernel: blocks [0, V_BLOCKS) compute v (Wᵀ·hidden, publish + signal);
// blocks [V_BLOCKS, ...) prefetch their enc rows, spin until v is published,
// then compute energies[b][l] = v[b] . enc[l][b]  (bias dropped: constant in
// l, softmax shift-invariant). Consumer reads g_v4 with __ldcg (L2-coherent):
// __ldg's read-only path is ILLEGAL on intra-kernel-mutated data (R5 bug).
// ---------------------------------------------------------------------------
__global__ void fused_kernel(const float* __restrict__ hidden,
                             const float* __restrict__ W,
                             const float* __restrict__ enc,
                             float* __restrict__ out) {
    const int t = threadIdx.x;             // 0..511

    if (blockIdx.x < V_BLOCKS) {
        // ===== v part: identical math to R4 v_kernel =====
        __shared__ float  hs[4][HIDDEN];
        __shared__ float4 part[4][16][8];

        const int bg = blockIdx.x >> 4;    // batch group 0..7
        const int hc = blockIdx.x & 15;    // h-chunk 0..15

        reinterpret_cast<float4*>(&hs[0][0])[t] =
            reinterpret_cast<const float4*>(hidden + bg * 4 * HIDDEN)[t];
        __syncthreads();

        const int og = t >> 3;             // o-group 0..63 (8 rows each)
        const int j  = t & 7;              // local h-quad 0..7
        const int jq = hc * 8 + j;         // global h-quad 0..127

        const float4* __restrict__ W4 = reinterpret_cast<const float4*>(W);

        float4 w[8];
        const int o0 = og * 8;
#pragma unroll
        for (int o = 0; o < 8; o++)
            w[o] = W4[(size_t)(o0 + o) * 128 + jq];

        float4 acc[4];
#pragma unroll
        for (int bi = 0; bi < 4; bi++) acc[bi] = make_float4(0.f, 0.f, 0.f, 0.f);

#pragma unroll
        for (int o = 0; o < 8; o++) {
#pragma unroll
            for (int bi = 0; bi < 4; bi++) {
                const float hv = hs[bi][o0 + o];
                acc[bi].x += hv * w[o].x;
                acc[bi].y += hv * w[o].y;
                acc[bi].z += hv * w[o].z;
                acc[bi].w += hv * w[o].w;
            }
        }

#pragma unroll
        for (int off = 8; off <= 16; off <<= 1) {
#pragma unroll
            for (int bi = 0; bi < 4; bi++) {
                acc[bi].x += __shfl_xor_sync(0xFFFFFFFFu, acc[bi].x, off);
                acc[bi].y += __shfl_xor_sync(0xFFFFFFFFu, acc[bi].y, off);
                acc[bi].z += __shfl_xor_sync(0xFFFFFFFFu, acc[bi].z, off);
                acc[bi].w += __shfl_xor_sync(0xFFFFFFFFu, acc[bi].w, off);
            }
        }

        const int lane = t & 31;
        const int warp = t >> 5;
        if (lane < 8) {
#pragma unroll
            for (int bi = 0; bi < 4; bi++) part[bi][warp][lane] = acc[bi];
        }
        __syncthreads();

        if (t < 32) {
            const int bi = t >> 3;
            const int jj = t & 7;
            float4 s = part[bi][0][jj];
#pragma unroll
            for (int wi = 1; wi < 16; wi++) {
                const float4 p = part[bi][wi][jj];
                s.x += p.x; s.y += p.y; s.z += p.z; s.w += p.w;
            }
            g_v4[(bg * 4 + bi) * 128 + hc * 8 + jj] = s;
        }
        __syncthreads();

        // Publish: make g_v4 writes visible at L2, then signal.
        if (t == 0) {
            __threadfence();
            atomicAdd(&g_vdone, 1);
        }
        return;
    }

    // ===== energy part =====
    const int r    = (blockIdx.x - V_BLOCKS) * E_WARPS + (t >> 5);
    const int lane = t & 31;
    const int b    = r & (BATCH - 1);
    const int l    = r >> 5;

    const float4* __restrict__ e4 =
        reinterpret_cast<const float4*>(enc) + (size_t)r * (HIDDEN / 4);

    // Front-batch the enc prefetch so its DRAM latency overlaps the spin.
    float4 a0 = __ldcs(&e4[lane]);
    float4 a1 = __ldcs(&e4[lane + 32]);
    float4 a2 = __ldcs(&e4[lane + 64]);
    float4 a3 = __ldcs(&e4[lane + 96]);

    // Wait until all v-blocks have published (acquire: fence after spin).
    if (t == 0) {
        while (atomicAdd(&g_vdone, 0) < V_BLOCKS) __nanosleep(128);
        __threadfence();
    }
    __syncthreads();

    // L2-coherent loads: g_v4 was written DURING this kernel.
    const float4* v4 = g_v4 + b * (HIDDEN / 4);
    const float4 w0 = __ldcg(&v4[lane]);
    const float4 w1 = __ldcg(&v4[lane + 32]);
    const float4 w2 = __ldcg(&v4[lane + 64]);
    const float4 w3 = __ldcg(&v4[lane + 96]);

    float acc = a0.x * w0.x + a0.y * w0.y + a0.z * w0.z + a0.w * w0.w;
    acc      += a1.x * w1.x + a1.y * w1.y + a1.z * w1.z + a1.w * w1.w;
    acc      += a2.x * w2.x + a2.y * w2.y + a2.z * w2.z + a2.w * w2.w;
    acc      += a3.x * w3.x + a3.y * w3.y + a3.z * w3.z + a3.w * w3.w;

#pragma unroll
    for (int off = 16; off; off >>= 1)
        acc += __shfl_xor_sync(0xFFFFFFFFu, acc, off);

    if (lane == 0) out[(size_t)b * MAX_LEN + l] = acc;
}

// ---------------------------------------------------------------------------
// Softmax over each row of out[32][4096]. 32 blocks x 1024 threads; each
// thread holds one float4 of the row. Block 0 also resets g_vdone for the
// NEXT graph replay (stream-ordered after fused_kernel; zero-init covers the
// first call).
// ---------------------------------------------------------------------------
__global__ void softmax_kernel(float* __restrict__ out) {
    __shared__ float red[32];

    const int b = blockIdx.x;
    const int t = threadIdx.x;

    if (b == 0 && t == 0) g_vdone = 0;   // reset for next launch

    float4* __restrict__ row4 =
        reinterpret_cast<float4*>(out) + (size_t)b * (MAX_LEN / 4);

    float4 x = row4[t];

    // --- max reduce ---
    float m = fmaxf(fmaxf(x.x, x.y), fmaxf(x.z, x.w));
#pragma unroll
    for (int o = 16; o; o >>= 1)
        m = fmaxf(m, __shfl_xor_sync(0xFFFFFFFFu, m, o));
    if ((t & 31) == 0) red[t >> 5] = m;
    __syncthreads();
    if (t < 32) {
        float mm = red[t];
#pragma unroll
        for (int o = 16; o; o >>= 1)
            mm = fmaxf(mm, __shfl_xor_sync(0xFFFFFFFFu, mm, o));
        if (t == 0) red[0] = mm;
    }
    __syncthreads();
    m = red[0];
    __syncthreads();   // protect red before reuse for sum

    // --- exp + sum reduce ---
    x.x = __expf(x.x - m);
    x.y = __expf(x.y - m);
    x.z = __expf(x.z - m);
    x.w = __expf(x.w - m);
    float s = x.x + x.y + x.z + x.w;
#pragma unroll
    for (int o = 16; o; o >>= 1)
        s += __shfl_xor_sync(0xFFFFFFFFu, s, o);
    if ((t & 31) == 0) red[t >> 5] = s;
    __syncthreads();
    if (t < 32) {
        float ss = red[t];
#pragma unroll
        for (int o = 16; o; o >>= 1)
            ss += __shfl_xor_sync(0xFFFFFFFFu, ss, o);
        if (t == 0) red[0] = ss;
    }
    __syncthreads();
    const float inv = 1.0f / red[0];

    x.x *= inv; x.y *= inv; x.z *= inv; x.w *= inv;
    row4[t] = x;
}

// ---------------------------------------------------------------------------
extern "C" void kernel_launch(void* const* d_in, const int* in_sizes, int n_in,
                              void* d_out, int out_size) {
    const float* hidden = (const float*)d_in[0];   // [1, 32, 512]
    const float* enc    = (const float*)d_in[1];   // [4096, 32, 512]
    const float* W      = (const float*)d_in[2];   // [512, 512]
    // d_in[3] = bias: provably irrelevant (constant shift under softmax)
    float* out = (float*)d_out;                    // [32, 1, 4096]

    const int rows    = MAX_LEN * BATCH;                // 131072
    const int eblocks = rows / E_WARPS;                 // 8192
    fused_kernel<<<V_BLOCKS + eblocks, 512>>>(hidden, W, enc, out);

    softmax_kernel<<<BATCH, MAX_LEN / 4>>>(out);
}